// round 15
// baseline (speedup 1.0000x reference)
#include <cuda_runtime.h>
#include <cuda_bf16.h>
#include <cstdint>

// Problem dims
#define BATCH 4
#define SEQ   2048
#define DIM   1024
#define MROWS (BATCH * SEQ)   // 8192

// Tile queue layout (LN folded into last ctx tile per rowblock)
#define QKV_TILES 1536
#define SC_TILES  2048
#define CTX_TILES 1024
#define SC_BASE   QKV_TILES
#define CTX_BASE  (QKV_TILES + SC_TILES)          // 3584
#define TOTAL_TILES (CTX_BASE + CTX_TILES)        // 4608

// ===========================================================================
// Scratch (device globals; no allocation anywhere)
// ===========================================================================
__device__ __align__(16) __nv_bfloat16 g_x[(size_t)MROWS * DIM];
__device__ __align__(16) __nv_bfloat16 g_wt[(size_t)3 * DIM * DIM];  // W^T [z][n][k]
__device__ __align__(16) __nv_bfloat16 g_q[(size_t)MROWS * DIM];    // pre-scaled by 1/32
__device__ __align__(16) __nv_bfloat16 g_k[(size_t)MROWS * DIM];
__device__ __align__(16) __nv_bfloat16 g_vt[(size_t)MROWS * DIM];   // V^T per batch [d][s]
__device__ __align__(16) __nv_bfloat16 g_p[(size_t)BATCH * SEQ * SEQ]; // unnormalized exp
__device__ __align__(16) float         g_psum[(size_t)MROWS * 32];  // per-row partial expsums
__device__ __align__(16) float         g_lnp[(size_t)MROWS * 32];   // [row][0:16]=sum,[16:32]=sumsq

// Packed scheduler state, single memset target.
__device__ int g_sched[512];
#define TILE_CTR (g_sched + 0)
#define CNT_Q    (g_sched + 1)     // 64, target 8
#define CNT_K    (g_sched + 65)    // 64, target 8
#define CNT_V    (g_sched + 129)   // 32, target 16
#define CNT_S    (g_sched + 161)   // 64, target 32
#define CNT_C    (g_sched + 225)   // 64, target 16

// ===========================================================================
// Baseline-ISA warp MMA helpers
// ===========================================================================
__device__ __forceinline__ uint32_t smem_u32(const void* p) {
    uint32_t a;
    asm("{ .reg .u64 t; cvta.to.shared.u64 t, %1; cvt.u32.u64 %0, t; }" : "=r"(a) : "l"(p));
    return a;
}

__device__ __forceinline__ void ldsm_x4(uint32_t& r0, uint32_t& r1, uint32_t& r2, uint32_t& r3,
                                        uint32_t addr) {
    asm volatile("ldmatrix.sync.aligned.m8n8.x4.shared.b16 {%0,%1,%2,%3}, [%4];"
                 : "=r"(r0), "=r"(r1), "=r"(r2), "=r"(r3) : "r"(addr));
}

__device__ __forceinline__ void mma16816(float* c, const uint32_t* a, const uint32_t* b) {
    asm volatile(
        "mma.sync.aligned.m16n8k16.row.col.f32.bf16.bf16.f32 "
        "{%0,%1,%2,%3}, {%4,%5,%6,%7}, {%8,%9}, {%0,%1,%2,%3};"
        : "+f"(c[0]), "+f"(c[1]), "+f"(c[2]), "+f"(c[3])
        : "r"(a[0]), "r"(a[1]), "r"(a[2]), "r"(a[3]), "r"(b[0]), "r"(b[1]));
}

__device__ __forceinline__ void cp_async16(uint32_t saddr, const void* gaddr) {
    asm volatile("cp.async.cg.shared.global [%0], [%1], 16;" :: "r"(saddr), "l"(gaddr));
}
__device__ __forceinline__ void cp_commit() { asm volatile("cp.async.commit_group;"); }
template <int N> __device__ __forceinline__ void cp_wait() {
    asm volatile("cp.async.wait_group %0;" :: "n"(N));
}

__device__ __forceinline__ uint32_t pack2(__nv_bfloat16 a, __nv_bfloat16 b) {
    __nv_bfloat162 p; p.x = a; p.y = b;
    return *reinterpret_cast<uint32_t*>(&p);
}

// Dependency wait: thread 0 spins on up to two counters, then acquire+sync.
__device__ __forceinline__ void wait2(const int* c1, int t1, const int* c2, int t2) {
    if (threadIdx.x == 0) {
        while (*(volatile const int*)c1 < t1) __nanosleep(128);
        while (*(volatile const int*)c2 < t2) __nanosleep(128);
        __threadfence();
    }
    __syncthreads();
}

// Completion signal: all threads fence, sync, one thread bumps the counter.
__device__ __forceinline__ void signal(int* c) {
    __threadfence();
    __syncthreads();
    if (threadIdx.x == 0) atomicAdd(c, 1);
}

// ===========================================================================
// GEMM mainloop templated on BN: acc[4][BN/16][4] += A[128,K] @ B[BN,K]^T
// ===========================================================================
#define ROW_B   144
#define TILE_A_B (128 * ROW_B)   // 18432

template <int BN>
__device__ __forceinline__ void load_stage(
    const __nv_bfloat16* __restrict__ A, int lda,
    const __nv_bfloat16* __restrict__ B, int ldb,
    int stg, uint32_t sbase, int buf, int t)
{
    constexpr int STAGE = TILE_A_B + BN * ROW_B;
    const size_t ko = (size_t)stg * 64;
    const uint32_t st = sbase + buf * STAGE;
#pragma unroll
    for (int i = 0; i < 8; i++) {
        const int c = t + i * 128;
        const int row = c >> 3, col = c & 7;
        cp_async16(st + row * ROW_B + col * 16,
                   reinterpret_cast<const char*>(A + (size_t)row * lda + ko) + col * 16);
    }
#pragma unroll
    for (int i = 0; i < BN / 16; i++) {
        const int c = t + i * 128;
        const int row = c >> 3, col = c & 7;
        cp_async16(st + TILE_A_B + row * ROW_B + col * 16,
                   reinterpret_cast<const char*>(B + (size_t)row * ldb + ko) + col * 16);
    }
    cp_commit();
}

template <int BN>
__device__ __forceinline__ void mma_mainloop(
    const __nv_bfloat16* __restrict__ A, int lda,
    const __nv_bfloat16* __restrict__ B, int ldb,
    int Kdim, char* smem, float acc[4][BN / 16][4])
{
    constexpr int NT = BN / 16;
    constexpr int STAGE = TILE_A_B + BN * ROW_B;
    const int t    = threadIdx.x;
    const int lane = t & 31;
    const int warp = t >> 5;
    const int wm   = warp & 1;
    const int wn   = warp >> 1;
    const uint32_t sbase = smem_u32(smem);

    const int aRow = lane & 15;
    const int aK   = (lane >> 4) & 1;
    const int bRow = (lane & 7) | (((lane >> 4) & 1) << 3);
    const int bK   = (lane >> 3) & 1;
    const uint32_t aBase = (wm * 64 + aRow) * ROW_B + aK * 16;
    const uint32_t bBase = TILE_A_B + (wn * (BN / 2) + bRow) * ROW_B + bK * 16;

#pragma unroll
    for (int i = 0; i < 4; i++)
#pragma unroll
        for (int j = 0; j < NT; j++)
#pragma unroll
            for (int q = 0; q < 4; q++) acc[i][j][q] = 0.0f;

    const int nstg = Kdim >> 6;
    load_stage<BN>(A, lda, B, ldb, 0, sbase, 0, t);

    for (int i = 0; i < nstg; i++) {
        const int buf = i & 1;
        const bool more = (i + 1 < nstg);
        if (more) load_stage<BN>(A, lda, B, ldb, i + 1, sbase, buf ^ 1, t);
        if (more) cp_wait<1>(); else cp_wait<0>();
        __syncthreads();

        const uint32_t st = sbase + buf * STAGE;
#pragma unroll
        for (int step = 0; step < 4; step++) {
            const uint32_t ao = st + aBase + step * 32;
            const uint32_t bo = st + bBase + step * 32;

            uint32_t a[4][4], b[NT][2];
#pragma unroll
            for (int mt = 0; mt < 4; mt++)
                ldsm_x4(a[mt][0], a[mt][1], a[mt][2], a[mt][3], ao + mt * 16 * ROW_B);
#pragma unroll
            for (int g = 0; g < BN / 32; g++) {
                uint32_t r0, r1, r2, r3;
                ldsm_x4(r0, r1, r2, r3, bo + g * 16 * ROW_B);
                b[2 * g][0] = r0;     b[2 * g][1] = r1;
                b[2 * g + 1][0] = r2; b[2 * g + 1][1] = r3;
            }
#pragma unroll
            for (int mt = 0; mt < 4; mt++)
#pragma unroll
                for (int nt = 0; nt < NT; nt++) mma16816(acc[mt][nt], a[mt], b[nt]);
        }
        __syncthreads();
    }
}

#define SMEM_128 (2 * (TILE_A_B + 128 * ROW_B))   // 73728
#define TSTRIDE 144

// ===========================================================================
// Phase bodies
// ===========================================================================
__device__ void do_qkv(int id, char* smem,
                       const float* bq, const float* bk, const float* bv)
{
    // id = y*24 + x*3 + z  (rowblock-major)
    const int y = id / 24;
    const int r = id % 24;
    const int x = r / 3;
    const int z = r % 3;
    const int m0 = y * 128, n0 = x * 128;

    const __nv_bfloat16* B = g_wt + (size_t)z * DIM * DIM;
    const float* bias = (z == 0) ? bq : (z == 1) ? bk : bv;

    float acc[4][8][4];
    mma_mainloop<128>(g_x + (size_t)m0 * DIM, DIM, B + (size_t)n0 * DIM, DIM, DIM, smem, acc);

    const int t = threadIdx.x;
    const int lane = t & 31, warp = t >> 5;
    const int wm = warp & 1, wn = warp >> 1;

    if (z < 2) {
        __nv_bfloat16* O = (z == 0) ? g_q : g_k;
        const float scale = (z == 0) ? 0.03125f : 1.0f;   // fold 1/sqrt(D) into Q
#pragma unroll
        for (int mt = 0; mt < 4; mt++)
#pragma unroll
            for (int nt = 0; nt < 8; nt++) {
                const int rr = m0 + wm * 64 + mt * 16 + (lane >> 2);
                const int cc = n0 + wn * 64 + nt * 8 + (lane & 3) * 2;
                const float b0 = bias[cc], b1 = bias[cc + 1];
#pragma unroll
                for (int h = 0; h < 2; h++) {
                    const size_t o = (size_t)(rr + h * 8) * DIM + cc;
                    *reinterpret_cast<uint32_t*>(O + o) =
                        pack2(__float2bfloat16((acc[mt][nt][2 * h] + b0) * scale),
                              __float2bfloat16((acc[mt][nt][2 * h + 1] + b1) * scale));
                }
            }
        signal((z == 0) ? CNT_Q + y : CNT_K + y);
    } else {
        // V: stage transposed tile in smem, write V^T (g_vt[b][d][s])
        __nv_bfloat16* stile = reinterpret_cast<__nv_bfloat16*>(smem);
#pragma unroll
        for (int mt = 0; mt < 4; mt++)
#pragma unroll
            for (int nt = 0; nt < 8; nt++) {
                const int rl = wm * 64 + mt * 16 + (lane >> 2);
                const int cl = wn * 64 + nt * 8 + (lane & 3) * 2;
                const float b0 = bias[n0 + cl], b1 = bias[n0 + cl + 1];
#pragma unroll
                for (int h = 0; h < 2; h++) {
                    stile[(cl)     * TSTRIDE + rl + h * 8] =
                        __float2bfloat16(acc[mt][nt][2 * h] + b0);
                    stile[(cl + 1) * TSTRIDE + rl + h * 8] =
                        __float2bfloat16(acc[mt][nt][2 * h + 1] + b1);
                }
            }
        __syncthreads();
        const int bb = m0 >> 11;
        const int s0 = m0 & 2047;
        __nv_bfloat16* T = g_vt + (size_t)bb * DIM * SEQ;
#pragma unroll
        for (int pass = 0; pass < 16; pass++) {
            const int dl = pass * 8 + (t >> 4);
            const int sc = (t & 15) * 8;
            uint4 v = *reinterpret_cast<const uint4*>(stile + dl * TSTRIDE + sc);
            *reinterpret_cast<uint4*>(T + (size_t)(n0 + dl) * SEQ + s0 + sc) = v;
        }
        signal(CNT_V + x * 4 + (y >> 4));
    }
}

__device__ void do_scores(int id, char* smem)
{
    // id = rb*32 + n ; rb = b*16 + m
    const int rb = id / 32;
    const int n  = id % 32;
    const int b  = rb / 16;
    const int m0 = (rb % 16) * 128;
    const int n0 = n * 64;

    wait2(CNT_Q + rb, 8, CNT_K + b * 16 + (n >> 1), 8);

    const size_t qo = (size_t)b * SEQ * DIM;
    float acc[4][4][4];
    mma_mainloop<64>(g_q + qo + (size_t)m0 * DIM, DIM,
                     g_k + qo + (size_t)n0 * DIM, DIM, DIM, smem, acc);

    const int t = threadIdx.x;
    const int lane = t & 31, warp = t >> 5;
    const int wm = warp & 1, wn = warp >> 1;
    __nv_bfloat16* out = g_p + (size_t)b * SEQ * SEQ;

    float rsum[4][2];
#pragma unroll
    for (int mt = 0; mt < 4; mt++) { rsum[mt][0] = 0.f; rsum[mt][1] = 0.f; }

#pragma unroll
    for (int mt = 0; mt < 4; mt++)
#pragma unroll
        for (int nt = 0; nt < 4; nt++) {
            const int rr = m0 + wm * 64 + mt * 16 + (lane >> 2);
            const int cc = n0 + wn * 32 + nt * 8 + (lane & 3) * 2;
#pragma unroll
            for (int h = 0; h < 2; h++) {
                float e0 = __expf(acc[mt][nt][2 * h]);       // Q pre-scaled by 1/32
                float e1 = __expf(acc[mt][nt][2 * h + 1]);
                *reinterpret_cast<uint32_t*>(out + (size_t)(rr + h * 8) * SEQ + cc) =
                    pack2(__float2bfloat16(e0), __float2bfloat16(e1));
                rsum[mt][h] += e0 + e1;
            }
        }

#pragma unroll
    for (int mt = 0; mt < 4; mt++)
#pragma unroll
        for (int h = 0; h < 2; h++) {
            rsum[mt][h] += __shfl_xor_sync(0xffffffffu, rsum[mt][h], 1);
            rsum[mt][h] += __shfl_xor_sync(0xffffffffu, rsum[mt][h], 2);
        }

    float* sums = reinterpret_cast<float*>(smem);   // [128][2]
    if ((lane & 3) == 0) {
#pragma unroll
        for (int mt = 0; mt < 4; mt++)
#pragma unroll
            for (int h = 0; h < 2; h++) {
                const int row = wm * 64 + mt * 16 + (lane >> 2) + h * 8;
                sums[row * 2 + wn] = rsum[mt][h];
            }
    }
    __syncthreads();
    if (t < 128) {
        float s = sums[t * 2] + sums[t * 2 + 1];
        g_psum[((size_t)b * SEQ + m0 + t) * 32 + n] = s;
    }
    signal(CNT_S + rb);
}

// LN body for one 32-row group (row0 = base row of this tile's group)
__device__ __forceinline__ void ln_rows(int row0,
                                        const float* gamma, const float* beta, float* io)
{
    const int warp = threadIdx.x >> 5, lane = threadIdx.x & 31;
    const int base = row0 + warp * 8;
#pragma unroll
    for (int j = 0; j < 8; j++) {
        const int row = base + j;
        float v1 = (lane < 16) ? g_lnp[(size_t)row * 32 + lane] : 0.f;
        float v2 = (lane < 16) ? g_lnp[(size_t)row * 32 + 16 + lane] : 0.f;
#pragma unroll
        for (int o = 16; o > 0; o >>= 1) {
            v1 += __shfl_xor_sync(0xffffffffu, v1, o);
            v2 += __shfl_xor_sync(0xffffffffu, v2, o);
        }
        const float mu = v1 * (1.0f / DIM);
        const float var = v2 * (1.0f / DIM) - mu * mu;
        const float w = rsqrtf(var + 1e-3f);

        float* p = io + (size_t)row * DIM;
#pragma unroll
        for (int i = 0; i < 8; i++) {
            const int idx = i * 128 + lane * 4;
            float4 v = *reinterpret_cast<const float4*>(p + idx);
            float4 g = *reinterpret_cast<const float4*>(gamma + idx);
            float4 bb = *reinterpret_cast<const float4*>(beta + idx);
            *reinterpret_cast<float4*>(p + idx) =
                make_float4((v.x - mu) * w * g.x + bb.x, (v.y - mu) * w * g.y + bb.y,
                            (v.z - mu) * w * g.z + bb.z, (v.w - mu) * w * g.w + bb.w);
        }
    }
}

__device__ void do_ctx(int id, char* smem, float* outp, const float* x,
                       const float* gamma, const float* beta)
{
    // id = rb*16 + n
    const int rb = id / 16;
    const int n  = id % 16;
    const int b  = rb / 16;
    const int m0 = (rb % 16) * 128;
    const int n0 = n * 64;
    const int t = threadIdx.x;
    const int lane = t & 31, warp = t >> 5;
    const int wm = warp & 1, wn = warp >> 1;
    const size_t rowbase = (size_t)b * SEQ;

    wait2(CNT_S + rb, 32, CNT_V + (n >> 1) * 4 + b, 16);

    // Prologue: 1/rowsum for this tile's 128 rows
    {
        float* sinv = reinterpret_cast<float*>(smem);
        if (t < 128) {
            const float4* pp =
                reinterpret_cast<const float4*>(g_psum + (rowbase + m0 + t) * 32);
            float s = 0.f;
#pragma unroll
            for (int j = 0; j < 8; j++) {
                float4 v = pp[j];
                s += (v.x + v.y) + (v.z + v.w);
            }
            sinv[t] = 1.0f / s;
        }
        __syncthreads();
    }
    float invr[4][2];
#pragma unroll
    for (int mt = 0; mt < 4; mt++)
#pragma unroll
        for (int h = 0; h < 2; h++)
            invr[mt][h] = reinterpret_cast<const float*>(smem)
                          [wm * 64 + mt * 16 + (lane >> 2) + h * 8];
    __syncthreads();

    float acc[4][4][4];
    mma_mainloop<64>(g_p + (size_t)b * SEQ * SEQ + (size_t)m0 * SEQ, SEQ,
                     g_vt + (size_t)b * (size_t)DIM * SEQ + (size_t)n0 * SEQ, SEQ,
                     SEQ, smem, acc);

    float* out = outp + rowbase * DIM;
    const float* xin = x + rowbase * DIM;

    float s1[4][2], s2[4][2];
#pragma unroll
    for (int mt = 0; mt < 4; mt++) { s1[mt][0] = s1[mt][1] = s2[mt][0] = s2[mt][1] = 0.f; }

#pragma unroll
    for (int mt = 0; mt < 4; mt++)
#pragma unroll
        for (int nt = 0; nt < 4; nt++) {
            const int rr = m0 + wm * 64 + mt * 16 + (lane >> 2);
            const int cc = n0 + wn * 32 + nt * 8 + (lane & 3) * 2;
#pragma unroll
            for (int h = 0; h < 2; h++) {
                const size_t o = (size_t)(rr + h * 8) * DIM + cc;
                float2 xi = *reinterpret_cast<const float2*>(xin + o);
                float v0 = acc[mt][nt][2 * h]     * invr[mt][h] + xi.x;
                float v1 = acc[mt][nt][2 * h + 1] * invr[mt][h] + xi.y;
                *reinterpret_cast<float2*>(out + o) = make_float2(v0, v1);
                s1[mt][h] += v0 + v1;
                s2[mt][h] += v0 * v0 + v1 * v1;
            }
        }

#pragma unroll
    for (int mt = 0; mt < 4; mt++)
#pragma unroll
        for (int h = 0; h < 2; h++) {
            s1[mt][h] += __shfl_xor_sync(0xffffffffu, s1[mt][h], 1);
            s1[mt][h] += __shfl_xor_sync(0xffffffffu, s1[mt][h], 2);
            s2[mt][h] += __shfl_xor_sync(0xffffffffu, s2[mt][h], 1);
            s2[mt][h] += __shfl_xor_sync(0xffffffffu, s2[mt][h], 2);
        }

    float* sums = reinterpret_cast<float*>(smem);
    if ((lane & 3) == 0) {
#pragma unroll
        for (int mt = 0; mt < 4; mt++)
#pragma unroll
            for (int h = 0; h < 2; h++) {
                const int row = wm * 64 + mt * 16 + (lane >> 2) + h * 8;
                sums[row * 4 + wn * 2 + 0] = s1[mt][h];
                sums[row * 4 + wn * 2 + 1] = s2[mt][h];
            }
    }
    __syncthreads();
    if (t < 128) {
        const size_t row = rowbase + m0 + t;
        g_lnp[row * 32 + n]      = sums[t * 4] + sums[t * 4 + 2];
        g_lnp[row * 32 + 16 + n] = sums[t * 4 + 1] + sums[t * 4 + 3];
    }

    // Completion + last-tile-inline LayerNorm for this rowblock.
    __threadfence();
    __syncthreads();
    __shared__ int s_last;
    if (t == 0) {
        int old = atomicAdd(CNT_C + rb, 1);
        s_last = (old == 15);
        if (old == 15) __threadfence();   // acquire: make peers' out/lnp visible
    }
    __syncthreads();
    if (s_last) {
        const int grow0 = (int)rowbase + m0;    // 128 rows of this rowblock
        ln_rows(grow0,       gamma, beta, outp);
        ln_rows(grow0 + 32,  gamma, beta, outp);
        ln_rows(grow0 + 64,  gamma, beta, outp);
        ln_rows(grow0 + 96,  gamma, beta, outp);
    }
}

// ===========================================================================
// Persistent megakernel
// ===========================================================================
__global__ void __launch_bounds__(128, 3) mega(
    float* __restrict__ out, const float* __restrict__ x,
    const float* __restrict__ bq, const float* __restrict__ bk,
    const float* __restrict__ bv,
    const float* __restrict__ gamma, const float* __restrict__ beta)
{
    extern __shared__ __align__(16) char smem[];
    __shared__ int s_tile;

    for (;;) {
        if (threadIdx.x == 0) s_tile = atomicAdd(TILE_CTR, 1);
        __syncthreads();
        const int tile = s_tile;
        if (tile >= TOTAL_TILES) break;

        if (tile < SC_BASE)        do_qkv(tile, smem, bq, bk, bv);
        else if (tile < CTX_BASE)  do_scores(tile - SC_BASE, smem);
        else                       do_ctx(tile - CTX_BASE, smem, out, x, gamma, beta);

        __syncthreads();   // protect s_tile before next grab
    }
}

// ===========================================================================
// Conversion kernel (full-grid, separate launch — max parallelism)
// ===========================================================================
__global__ void __launch_bounds__(256) conv_all(
    const float* __restrict__ x,
    const float* __restrict__ Wq, const float* __restrict__ Wk, const float* __restrict__ Wv)
{
    const int z = blockIdx.z;
    if (z < 3) {
        __shared__ float s[32][33];
        const float* W = (z == 0) ? Wq : (z == 1) ? Wk : Wv;
        __nv_bfloat16* o = g_wt + (size_t)z * DIM * DIM;
        const int n0 = blockIdx.x * 32, k0 = blockIdx.y * 32;
        const int tx = threadIdx.x & 31, ty = threadIdx.x >> 5;
#pragma unroll
        for (int i = 0; i < 32; i += 8)
            s[ty + i][tx] = W[(size_t)(k0 + ty + i) * DIM + n0 + tx];
        __syncthreads();
#pragma unroll
        for (int i = 0; i < 32; i += 8)
            o[(size_t)(n0 + ty + i) * DIM + k0 + tx] = __float2bfloat16(s[tx][ty + i]);
    } else {
        const int bid = blockIdx.y * 32 + blockIdx.x;
        const int base = bid * 2048 + threadIdx.x;
#pragma unroll
        for (int k = 0; k < 8; k++) {
            const int i = base + k * 256;
            float4 v = reinterpret_cast<const float4*>(x)[i];
            reinterpret_cast<uint2*>(g_x)[i] =
                make_uint2(pack2(__float2bfloat16(v.x), __float2bfloat16(v.y)),
                           pack2(__float2bfloat16(v.z), __float2bfloat16(v.w)));
        }
    }
}

// ===========================================================================
// Launch
// ===========================================================================
extern "C" void kernel_launch(void* const* d_in, const int* in_sizes, int n_in,
                              void* d_out, int out_size)
{
    const float* X  = (const float*)d_in[0];
    const float* Wq = (const float*)d_in[1];
    const float* bq = (const float*)d_in[2];
    const float* Wk = (const float*)d_in[3];
    const float* bk = (const float*)d_in[4];
    const float* Wv = (const float*)d_in[5];
    const float* bv = (const float*)d_in[6];
    const float* gm = (const float*)d_in[7];
    const float* bt = (const float*)d_in[8];
    float* out = (float*)d_out;

    cudaFuncSetAttribute(mega, cudaFuncAttributeMaxDynamicSharedMemorySize, SMEM_128);

    // reset scheduler state (single async memset; graph-capturable)
    void* sched_addr = nullptr;
    cudaGetSymbolAddress(&sched_addr, g_sched);
    cudaMemsetAsync(sched_addr, 0, 512 * sizeof(int));

    // conversions at full grid parallelism
    conv_all<<<dim3(32, 32, 4), 256>>>(X, Wq, Wk, Wv);

    // persistent megakernel: qkv -> scores -> ctx(+inline LN) via tile queue
    mega<<<456, 128, SMEM_128>>>(out, X, bq, bk, bv, gm, bt);
}

// round 16
// speedup vs baseline: 1.0801x; 1.0801x over previous
#include <cuda_runtime.h>
#include <cuda_bf16.h>
#include <cstdint>

// Problem dims
#define BATCH 4
#define SEQ   2048
#define DIM   1024
#define MROWS (BATCH * SEQ)   // 8192

// Tile queue layout (all GEMM tiles BN=128)
#define QKV_TILES 1536
#define SC_TILES  1024
#define CTX_TILES 512
#define LN_TILES  256
#define SC_BASE   QKV_TILES                       // 1536
#define CTX_BASE  (SC_BASE + SC_TILES)            // 2560
#define LN_BASE   (CTX_BASE + CTX_TILES)          // 3072
#define TOTAL_TILES (LN_BASE + LN_TILES)          // 3328

// ===========================================================================
// Scratch (device globals; no allocation anywhere)
// ===========================================================================
__device__ __align__(16) __nv_bfloat16 g_x[(size_t)MROWS * DIM];
__device__ __align__(16) __nv_bfloat16 g_wt[(size_t)3 * DIM * DIM];  // W^T [z][n][k]
__device__ __align__(16) __nv_bfloat16 g_q[(size_t)MROWS * DIM];
__device__ __align__(16) __nv_bfloat16 g_k[(size_t)MROWS * DIM];
__device__ __align__(16) __nv_bfloat16 g_vt[(size_t)MROWS * DIM];   // V^T per batch [d][s]
__device__ __align__(16) __nv_bfloat16 g_p[(size_t)BATCH * SEQ * SEQ]; // unnormalized exp
__device__ __align__(16) float         g_psum[(size_t)MROWS * 16];  // per-row partial expsums
__device__ __align__(16) float         g_lnp[(size_t)MROWS * 16];   // [row][0:8]=sum,[8:16]=sumsq

// Packed scheduler state, single memset target.
__device__ int g_sched[512];
#define TILE_CTR (g_sched + 0)
#define CNT_Q    (g_sched + 1)     // 64, target 8
#define CNT_K    (g_sched + 65)    // 64, target 8
#define CNT_V    (g_sched + 129)   // 32, target 16
#define CNT_S    (g_sched + 161)   // 64, target 16
#define CNT_C    (g_sched + 225)   // 64, target 8

// ===========================================================================
// Baseline-ISA warp MMA helpers
// ===========================================================================
__device__ __forceinline__ uint32_t smem_u32(const void* p) {
    uint32_t a;
    asm("{ .reg .u64 t; cvta.to.shared.u64 t, %1; cvt.u32.u64 %0, t; }" : "=r"(a) : "l"(p));
    return a;
}

__device__ __forceinline__ void ldsm_x4(uint32_t& r0, uint32_t& r1, uint32_t& r2, uint32_t& r3,
                                        uint32_t addr) {
    asm volatile("ldmatrix.sync.aligned.m8n8.x4.shared.b16 {%0,%1,%2,%3}, [%4];"
                 : "=r"(r0), "=r"(r1), "=r"(r2), "=r"(r3) : "r"(addr));
}

__device__ __forceinline__ void mma16816(float* c, const uint32_t* a, const uint32_t* b) {
    asm volatile(
        "mma.sync.aligned.m16n8k16.row.col.f32.bf16.bf16.f32 "
        "{%0,%1,%2,%3}, {%4,%5,%6,%7}, {%8,%9}, {%0,%1,%2,%3};"
        : "+f"(c[0]), "+f"(c[1]), "+f"(c[2]), "+f"(c[3])
        : "r"(a[0]), "r"(a[1]), "r"(a[2]), "r"(a[3]), "r"(b[0]), "r"(b[1]));
}

__device__ __forceinline__ void cp_async16(uint32_t saddr, const void* gaddr) {
    asm volatile("cp.async.cg.shared.global [%0], [%1], 16;" :: "r"(saddr), "l"(gaddr));
}
__device__ __forceinline__ void cp_commit() { asm volatile("cp.async.commit_group;"); }
template <int N> __device__ __forceinline__ void cp_wait() {
    asm volatile("cp.async.wait_group %0;" :: "n"(N));
}

__device__ __forceinline__ uint32_t pack2(__nv_bfloat16 a, __nv_bfloat16 b) {
    __nv_bfloat162 p; p.x = a; p.y = b;
    return *reinterpret_cast<uint32_t*>(&p);
}

// Dependency wait: thread 0 spins on up to two counters, then acquire+sync.
__device__ __forceinline__ void wait2(const int* c1, int t1, const int* c2, int t2) {
    if (threadIdx.x == 0) {
        while (*(volatile const int*)c1 < t1) __nanosleep(128);
        while (*(volatile const int*)c2 < t2) __nanosleep(128);
        __threadfence();
    }
    __syncthreads();
}

// Completion signal: all threads fence, sync, one thread bumps the counter.
__device__ __forceinline__ void signal(int* c) {
    __threadfence();
    __syncthreads();
    if (threadIdx.x == 0) atomicAdd(c, 1);
}

// ===========================================================================
// GEMM mainloop (BN=128): acc[4][8][4] += A[128,K] @ B[128,K]^T
//   128 threads = 4 warps (2M x 2N); warp tile 64x64. K-chunk 64.
// ===========================================================================
#define ROW_B   144
#define TILE_A_B (128 * ROW_B)   // 18432
#define STAGE_B  (2 * TILE_A_B)  // 36864
#define SMEM_128 (2 * STAGE_B)   // 73728

__device__ __forceinline__ void load_stage(
    const __nv_bfloat16* __restrict__ A, int lda,
    const __nv_bfloat16* __restrict__ B, int ldb,
    int stg, uint32_t sbase, int buf, int t)
{
    const size_t ko = (size_t)stg * 64;
    const uint32_t st = sbase + buf * STAGE_B;
#pragma unroll
    for (int i = 0; i < 8; i++) {
        const int c = t + i * 128;
        const int row = c >> 3, col = c & 7;
        cp_async16(st + row * ROW_B + col * 16,
                   reinterpret_cast<const char*>(A + (size_t)row * lda + ko) + col * 16);
    }
#pragma unroll
    for (int i = 0; i < 8; i++) {
        const int c = t + i * 128;
        const int row = c >> 3, col = c & 7;
        cp_async16(st + TILE_A_B + row * ROW_B + col * 16,
                   reinterpret_cast<const char*>(B + (size_t)row * ldb + ko) + col * 16);
    }
    cp_commit();
}

__device__ __forceinline__ void mma_mainloop(
    const __nv_bfloat16* __restrict__ A, int lda,
    const __nv_bfloat16* __restrict__ B, int ldb,
    int Kdim, char* smem, float acc[4][8][4])
{
    const int t    = threadIdx.x;
    const int lane = t & 31;
    const int warp = t >> 5;
    const int wm   = warp & 1;
    const int wn   = warp >> 1;
    const uint32_t sbase = smem_u32(smem);

    const int aRow = lane & 15;
    const int aK   = (lane >> 4) & 1;
    const int bRow = (lane & 7) | (((lane >> 4) & 1) << 3);
    const int bK   = (lane >> 3) & 1;
    const uint32_t aBase = (wm * 64 + aRow) * ROW_B + aK * 16;
    const uint32_t bBase = TILE_A_B + (wn * 64 + bRow) * ROW_B + bK * 16;

#pragma unroll
    for (int i = 0; i < 4; i++)
#pragma unroll
        for (int j = 0; j < 8; j++)
#pragma unroll
            for (int q = 0; q < 4; q++) acc[i][j][q] = 0.0f;

    const int nstg = Kdim >> 6;
    load_stage(A, lda, B, ldb, 0, sbase, 0, t);

    for (int i = 0; i < nstg; i++) {
        const int buf = i & 1;
        const bool more = (i + 1 < nstg);
        if (more) load_stage(A, lda, B, ldb, i + 1, sbase, buf ^ 1, t);
        if (more) cp_wait<1>(); else cp_wait<0>();
        __syncthreads();

        const uint32_t st = sbase + buf * STAGE_B;
#pragma unroll
        for (int step = 0; step < 4; step++) {
            const uint32_t ao = st + aBase + step * 32;
            const uint32_t bo = st + bBase + step * 32;

            uint32_t a[4][4], b[8][2];
#pragma unroll
            for (int mt = 0; mt < 4; mt++)
                ldsm_x4(a[mt][0], a[mt][1], a[mt][2], a[mt][3], ao + mt * 16 * ROW_B);
#pragma unroll
            for (int g = 0; g < 4; g++) {
                uint32_t r0, r1, r2, r3;
                ldsm_x4(r0, r1, r2, r3, bo + g * 16 * ROW_B);
                b[2 * g][0] = r0;     b[2 * g][1] = r1;
                b[2 * g + 1][0] = r2; b[2 * g + 1][1] = r3;
            }
#pragma unroll
            for (int mt = 0; mt < 4; mt++)
#pragma unroll
                for (int nt = 0; nt < 8; nt++) mma16816(acc[mt][nt], a[mt], b[nt]);
        }
        __syncthreads();
    }
}

#define TSTRIDE 144

// ===========================================================================
// Phase bodies
// ===========================================================================
__device__ void do_qkv(int id, char* smem,
                       const float* bq, const float* bk, const float* bv)
{
    // id = y*24 + x*3 + z  (rowblock-major)
    const int y = id / 24;
    const int r = id % 24;
    const int x = r / 3;
    const int z = r % 3;
    const int m0 = y * 128, n0 = x * 128;

    const __nv_bfloat16* B = g_wt + (size_t)z * DIM * DIM;
    const float* bias = (z == 0) ? bq : (z == 1) ? bk : bv;

    float acc[4][8][4];
    mma_mainloop(g_x + (size_t)m0 * DIM, DIM, B + (size_t)n0 * DIM, DIM, DIM, smem, acc);

    const int t = threadIdx.x;
    const int lane = t & 31, warp = t >> 5;
    const int wm = warp & 1, wn = warp >> 1;

    if (z < 2) {
        __nv_bfloat16* O = (z == 0) ? g_q : g_k;
#pragma unroll
        for (int mt = 0; mt < 4; mt++)
#pragma unroll
            for (int nt = 0; nt < 8; nt++) {
                const int rr = m0 + wm * 64 + mt * 16 + (lane >> 2);
                const int cc = n0 + wn * 64 + nt * 8 + (lane & 3) * 2;
                const float b0 = bias[cc], b1 = bias[cc + 1];
#pragma unroll
                for (int h = 0; h < 2; h++) {
                    const size_t o = (size_t)(rr + h * 8) * DIM + cc;
                    *reinterpret_cast<uint32_t*>(O + o) =
                        pack2(__float2bfloat16(acc[mt][nt][2 * h] + b0),
                              __float2bfloat16(acc[mt][nt][2 * h + 1] + b1));
                }
            }
        signal((z == 0) ? CNT_Q + y : CNT_K + y);
    } else {
        // V: stage transposed tile in smem, write V^T (g_vt[b][d][s])
        __nv_bfloat16* stile = reinterpret_cast<__nv_bfloat16*>(smem);
#pragma unroll
        for (int mt = 0; mt < 4; mt++)
#pragma unroll
            for (int nt = 0; nt < 8; nt++) {
                const int rl = wm * 64 + mt * 16 + (lane >> 2);
                const int cl = wn * 64 + nt * 8 + (lane & 3) * 2;
                const float b0 = bias[n0 + cl], b1 = bias[n0 + cl + 1];
#pragma unroll
                for (int h = 0; h < 2; h++) {
                    stile[(cl)     * TSTRIDE + rl + h * 8] =
                        __float2bfloat16(acc[mt][nt][2 * h] + b0);
                    stile[(cl + 1) * TSTRIDE + rl + h * 8] =
                        __float2bfloat16(acc[mt][nt][2 * h + 1] + b1);
                }
            }
        __syncthreads();
        const int bb = m0 >> 11;
        const int s0 = m0 & 2047;
        __nv_bfloat16* T = g_vt + (size_t)bb * DIM * SEQ;
#pragma unroll
        for (int pass = 0; pass < 16; pass++) {
            const int dl = pass * 8 + (t >> 4);
            const int sc = (t & 15) * 8;
            uint4 v = *reinterpret_cast<const uint4*>(stile + dl * TSTRIDE + sc);
            *reinterpret_cast<uint4*>(T + (size_t)(n0 + dl) * SEQ + s0 + sc) = v;
        }
        signal(CNT_V + x * 4 + (y >> 4));
    }
}

// scores (BN=128) + exp + partial row sums: P (bf16) + g_psum[row][16]
__device__ void do_scores(int id, char* smem)
{
    // id = rb*16 + n ; rb = b*16 + m
    const int rb = id / 16;
    const int n  = id % 16;
    const int b  = rb / 16;
    const int m0 = (rb % 16) * 128;
    const int n0 = n * 128;

    wait2(CNT_Q + rb, 8, CNT_K + b * 16 + n, 8);

    const size_t qo = (size_t)b * SEQ * DIM;
    float acc[4][8][4];
    mma_mainloop(g_q + qo + (size_t)m0 * DIM, DIM,
                 g_k + qo + (size_t)n0 * DIM, DIM, DIM, smem, acc);

    const int t = threadIdx.x;
    const int lane = t & 31, warp = t >> 5;
    const int wm = warp & 1, wn = warp >> 1;
    __nv_bfloat16* out = g_p + (size_t)b * SEQ * SEQ;

    float rsum[4][2];
#pragma unroll
    for (int mt = 0; mt < 4; mt++) { rsum[mt][0] = 0.f; rsum[mt][1] = 0.f; }

#pragma unroll
    for (int mt = 0; mt < 4; mt++)
#pragma unroll
        for (int nt = 0; nt < 8; nt++) {
            const int rr = m0 + wm * 64 + mt * 16 + (lane >> 2);
            const int cc = n0 + wn * 64 + nt * 8 + (lane & 3) * 2;
#pragma unroll
            for (int h = 0; h < 2; h++) {
                float e0 = __expf(acc[mt][nt][2 * h]     * 0.03125f);
                float e1 = __expf(acc[mt][nt][2 * h + 1] * 0.03125f);
                *reinterpret_cast<uint32_t*>(out + (size_t)(rr + h * 8) * SEQ + cc) =
                    pack2(__float2bfloat16(e0), __float2bfloat16(e1));
                rsum[mt][h] += e0 + e1;
            }
        }

#pragma unroll
    for (int mt = 0; mt < 4; mt++)
#pragma unroll
        for (int h = 0; h < 2; h++) {
            rsum[mt][h] += __shfl_xor_sync(0xffffffffu, rsum[mt][h], 1);
            rsum[mt][h] += __shfl_xor_sync(0xffffffffu, rsum[mt][h], 2);
        }

    float* sums = reinterpret_cast<float*>(smem);   // [128][2]
    if ((lane & 3) == 0) {
#pragma unroll
        for (int mt = 0; mt < 4; mt++)
#pragma unroll
            for (int h = 0; h < 2; h++) {
                const int row = wm * 64 + mt * 16 + (lane >> 2) + h * 8;
                sums[row * 2 + wn] = rsum[mt][h];
            }
    }
    __syncthreads();
    if (t < 128) {
        float s = sums[t * 2] + sums[t * 2 + 1];
        g_psum[((size_t)b * SEQ + m0 + t) * 16 + n] = s;
    }
    signal(CNT_S + rb);
}

// ctx (BN=128): (P @ V^T normalized) + X residual; LN partials to g_lnp[row][16]
__device__ void do_ctx(int id, char* smem, float* outp, const float* x)
{
    // id = rb*8 + n
    const int rb = id / 8;
    const int n  = id % 8;
    const int b  = rb / 16;
    const int m0 = (rb % 16) * 128;
    const int n0 = n * 128;
    const int t = threadIdx.x;
    const int lane = t & 31, warp = t >> 5;
    const int wm = warp & 1, wn = warp >> 1;
    const size_t rowbase = (size_t)b * SEQ;

    wait2(CNT_S + rb, 16, CNT_V + n * 4 + b, 16);

    // Prologue: 1/rowsum for this tile's 128 rows (16 partials each)
    {
        float* sinv = reinterpret_cast<float*>(smem);
        if (t < 128) {
            const float4* pp =
                reinterpret_cast<const float4*>(g_psum + (rowbase + m0 + t) * 16);
            float4 a = pp[0], bb = pp[1], c = pp[2], d = pp[3];
            float s = ((a.x + a.y) + (a.z + a.w)) + ((bb.x + bb.y) + (bb.z + bb.w)) +
                      ((c.x + c.y) + (c.z + c.w)) + ((d.x + d.y) + (d.z + d.w));
            sinv[t] = 1.0f / s;
        }
        __syncthreads();
    }
    float invr[4][2];
#pragma unroll
    for (int mt = 0; mt < 4; mt++)
#pragma unroll
        for (int h = 0; h < 2; h++)
            invr[mt][h] = reinterpret_cast<const float*>(smem)
                          [wm * 64 + mt * 16 + (lane >> 2) + h * 8];
    __syncthreads();

    float acc[4][8][4];
    mma_mainloop(g_p + (size_t)b * SEQ * SEQ + (size_t)m0 * SEQ, SEQ,
                 g_vt + (size_t)b * (size_t)DIM * SEQ + (size_t)n0 * SEQ, SEQ,
                 SEQ, smem, acc);

    float* out = outp + rowbase * DIM;
    const float* xin = x + rowbase * DIM;

    float s1[4][2], s2[4][2];
#pragma unroll
    for (int mt = 0; mt < 4; mt++) { s1[mt][0] = s1[mt][1] = s2[mt][0] = s2[mt][1] = 0.f; }

#pragma unroll
    for (int mt = 0; mt < 4; mt++)
#pragma unroll
        for (int nt = 0; nt < 8; nt++) {
            const int rr = m0 + wm * 64 + mt * 16 + (lane >> 2);
            const int cc = n0 + wn * 64 + nt * 8 + (lane & 3) * 2;
#pragma unroll
            for (int h = 0; h < 2; h++) {
                const size_t o = (size_t)(rr + h * 8) * DIM + cc;
                float2 xi = *reinterpret_cast<const float2*>(xin + o);
                float v0 = acc[mt][nt][2 * h]     * invr[mt][h] + xi.x;
                float v1 = acc[mt][nt][2 * h + 1] * invr[mt][h] + xi.y;
                *reinterpret_cast<float2*>(out + o) = make_float2(v0, v1);
                s1[mt][h] += v0 + v1;
                s2[mt][h] += v0 * v0 + v1 * v1;
            }
        }

#pragma unroll
    for (int mt = 0; mt < 4; mt++)
#pragma unroll
        for (int h = 0; h < 2; h++) {
            s1[mt][h] += __shfl_xor_sync(0xffffffffu, s1[mt][h], 1);
            s1[mt][h] += __shfl_xor_sync(0xffffffffu, s1[mt][h], 2);
            s2[mt][h] += __shfl_xor_sync(0xffffffffu, s2[mt][h], 1);
            s2[mt][h] += __shfl_xor_sync(0xffffffffu, s2[mt][h], 2);
        }

    float* sums = reinterpret_cast<float*>(smem);   // [128][2 warps][2 stats]
    if ((lane & 3) == 0) {
#pragma unroll
        for (int mt = 0; mt < 4; mt++)
#pragma unroll
            for (int h = 0; h < 2; h++) {
                const int row = wm * 64 + mt * 16 + (lane >> 2) + h * 8;
                sums[row * 4 + wn * 2 + 0] = s1[mt][h];
                sums[row * 4 + wn * 2 + 1] = s2[mt][h];
            }
    }
    __syncthreads();
    if (t < 128) {
        const size_t row = rowbase + m0 + t;
        g_lnp[row * 16 + n]     = sums[t * 4] + sums[t * 4 + 2];
        g_lnp[row * 16 + 8 + n] = sums[t * 4 + 1] + sums[t * 4 + 3];
    }
    signal(CNT_C + rb);
}

__device__ void do_ln(int id, const float* gamma, const float* beta, float* io)
{
    wait2(CNT_C + (id >> 2), 8, CNT_C + (id >> 2), 8);

    const int warp = threadIdx.x >> 5, lane = threadIdx.x & 31;
    const int row0 = id * 32 + warp * 8;
#pragma unroll
    for (int j = 0; j < 8; j++) {
        const int row = row0 + j;
        float v1 = (lane < 8) ? g_lnp[(size_t)row * 16 + lane] : 0.f;
        float v2 = (lane < 8) ? g_lnp[(size_t)row * 16 + 8 + lane] : 0.f;
#pragma unroll
        for (int o = 16; o > 0; o >>= 1) {
            v1 += __shfl_xor_sync(0xffffffffu, v1, o);
            v2 += __shfl_xor_sync(0xffffffffu, v2, o);
        }
        const float mu = v1 * (1.0f / DIM);
        const float var = v2 * (1.0f / DIM) - mu * mu;
        const float w = rsqrtf(var + 1e-3f);

        float* p = io + (size_t)row * DIM;
#pragma unroll
        for (int i = 0; i < 8; i++) {
            const int idx = i * 128 + lane * 4;
            float4 v = *reinterpret_cast<const float4*>(p + idx);
            float4 g = *reinterpret_cast<const float4*>(gamma + idx);
            float4 bb = *reinterpret_cast<const float4*>(beta + idx);
            *reinterpret_cast<float4*>(p + idx) =
                make_float4((v.x - mu) * w * g.x + bb.x, (v.y - mu) * w * g.y + bb.y,
                            (v.z - mu) * w * g.z + bb.z, (v.w - mu) * w * g.w + bb.w);
        }
    }
}

// ===========================================================================
// Persistent megakernel
// ===========================================================================
__global__ void __launch_bounds__(128, 3) mega(
    float* __restrict__ out, const float* __restrict__ x,
    const float* __restrict__ bq, const float* __restrict__ bk,
    const float* __restrict__ bv,
    const float* __restrict__ gamma, const float* __restrict__ beta)
{
    extern __shared__ __align__(16) char smem[];
    __shared__ int s_tile;

    for (;;) {
        if (threadIdx.x == 0) s_tile = atomicAdd(TILE_CTR, 1);
        __syncthreads();
        const int tile = s_tile;
        if (tile >= TOTAL_TILES) break;

        if (tile < SC_BASE)        do_qkv(tile, smem, bq, bk, bv);
        else if (tile < CTX_BASE)  do_scores(tile - SC_BASE, smem);
        else if (tile < LN_BASE)   do_ctx(tile - CTX_BASE, smem, out, x);
        else                       do_ln(tile - LN_BASE, gamma, beta, out);

        __syncthreads();   // protect s_tile before next grab
    }
}

// ===========================================================================
// Conversion kernel (full-grid, separate launch — max parallelism)
// ===========================================================================
__global__ void __launch_bounds__(256) conv_all(
    const float* __restrict__ x,
    const float* __restrict__ Wq, const float* __restrict__ Wk, const float* __restrict__ Wv)
{
    const int z = blockIdx.z;
    if (z < 3) {
        __shared__ float s[32][33];
        const float* W = (z == 0) ? Wq : (z == 1) ? Wk : Wv;
        __nv_bfloat16* o = g_wt + (size_t)z * DIM * DIM;
        const int n0 = blockIdx.x * 32, k0 = blockIdx.y * 32;
        const int tx = threadIdx.x & 31, ty = threadIdx.x >> 5;
#pragma unroll
        for (int i = 0; i < 32; i += 8)
            s[ty + i][tx] = W[(size_t)(k0 + ty + i) * DIM + n0 + tx];
        __syncthreads();
#pragma unroll
        for (int i = 0; i < 32; i += 8)
            o[(size_t)(n0 + ty + i) * DIM + k0 + tx] = __float2bfloat16(s[tx][ty + i]);
    } else {
        const int bid = blockIdx.y * 32 + blockIdx.x;
        const int base = bid * 2048 + threadIdx.x;
#pragma unroll
        for (int k = 0; k < 8; k++) {
            const int i = base + k * 256;
            float4 v = reinterpret_cast<const float4*>(x)[i];
            reinterpret_cast<uint2*>(g_x)[i] =
                make_uint2(pack2(__float2bfloat16(v.x), __float2bfloat16(v.y)),
                           pack2(__float2bfloat16(v.z), __float2bfloat16(v.w)));
        }
    }
}

// ===========================================================================
// Launch
// ===========================================================================
extern "C" void kernel_launch(void* const* d_in, const int* in_sizes, int n_in,
                              void* d_out, int out_size)
{
    const float* X  = (const float*)d_in[0];
    const float* Wq = (const float*)d_in[1];
    const float* bq = (const float*)d_in[2];
    const float* Wk = (const float*)d_in[3];
    const float* bk = (const float*)d_in[4];
    const float* Wv = (const float*)d_in[5];
    const float* bv = (const float*)d_in[6];
    const float* gm = (const float*)d_in[7];
    const float* bt = (const float*)d_in[8];
    float* out = (float*)d_out;

    cudaFuncSetAttribute(mega, cudaFuncAttributeMaxDynamicSharedMemorySize, SMEM_128);

    // reset scheduler state (single async memset; graph-capturable)
    void* sched_addr = nullptr;
    cudaGetSymbolAddress(&sched_addr, g_sched);
    cudaMemsetAsync(sched_addr, 0, 512 * sizeof(int));

    // conversions at full grid parallelism
    conv_all<<<dim3(32, 32, 4), 256>>>(X, Wq, Wk, Wv);

    // persistent megakernel: qkv -> scores -> ctx -> LN via tile queue
    mega<<<456, 128, SMEM_128>>>(out, X, bq, bk, bv, gm, bt);
}

// round 17
// speedup vs baseline: 1.0827x; 1.0024x over previous
#include <cuda_runtime.h>
#include <cuda_bf16.h>
#include <cstdint>

// Problem dims
#define BATCH 4
#define SEQ   2048
#define DIM   1024
#define MROWS (BATCH * SEQ)   // 8192

// Tile queue layout (all GEMM tiles BN=128)
#define QKV_TILES 1536
#define SC_TILES  1024
#define CTX_TILES 512
#define LN_TILES  256
#define SC_BASE   QKV_TILES                       // 1536
#define CTX_BASE  (SC_BASE + SC_TILES)            // 2560
#define LN_BASE   (CTX_BASE + CTX_TILES)          // 3072
#define TOTAL_TILES (LN_BASE + LN_TILES)          // 3328

// ===========================================================================
// Scratch (device globals; no allocation anywhere)
// ===========================================================================
__device__ __align__(16) __nv_bfloat16 g_x[(size_t)MROWS * DIM];
__device__ __align__(16) __nv_bfloat16 g_wt[(size_t)3 * DIM * DIM];  // W^T [z][n][k]
__device__ __align__(16) __nv_bfloat16 g_q[(size_t)MROWS * DIM];
__device__ __align__(16) __nv_bfloat16 g_k[(size_t)MROWS * DIM];
__device__ __align__(16) __nv_bfloat16 g_vt[(size_t)MROWS * DIM];   // V^T per batch [d][s]
__device__ __align__(16) __nv_bfloat16 g_p[(size_t)BATCH * SEQ * SEQ]; // unnormalized exp
__device__ __align__(16) float         g_psum[(size_t)MROWS * 16];  // per-row partial expsums
__device__ __align__(16) float         g_lnp[(size_t)MROWS * 16];   // [row][0:8]=sum,[8:16]=sumsq

// Packed scheduler state, single memset target.
__device__ int g_sched[512];
#define TILE_CTR (g_sched + 0)
#define CNT_Q    (g_sched + 1)     // 64, target 8
#define CNT_K    (g_sched + 65)    // 64, target 8
#define CNT_V    (g_sched + 129)   // 32, target 16
#define CNT_S    (g_sched + 161)   // 64, target 16
#define CNT_C    (g_sched + 225)   // 64, target 8

// ===========================================================================
// Baseline-ISA warp MMA helpers
// ===========================================================================
__device__ __forceinline__ uint32_t smem_u32(const void* p) {
    uint32_t a;
    asm("{ .reg .u64 t; cvta.to.shared.u64 t, %1; cvt.u32.u64 %0, t; }" : "=r"(a) : "l"(p));
    return a;
}

__device__ __forceinline__ void ldsm_x4(uint32_t& r0, uint32_t& r1, uint32_t& r2, uint32_t& r3,
                                        uint32_t addr) {
    asm volatile("ldmatrix.sync.aligned.m8n8.x4.shared.b16 {%0,%1,%2,%3}, [%4];"
                 : "=r"(r0), "=r"(r1), "=r"(r2), "=r"(r3) : "r"(addr));
}

__device__ __forceinline__ void mma16816(float* c, const uint32_t* a, const uint32_t* b) {
    asm volatile(
        "mma.sync.aligned.m16n8k16.row.col.f32.bf16.bf16.f32 "
        "{%0,%1,%2,%3}, {%4,%5,%6,%7}, {%8,%9}, {%0,%1,%2,%3};"
        : "+f"(c[0]), "+f"(c[1]), "+f"(c[2]), "+f"(c[3])
        : "r"(a[0]), "r"(a[1]), "r"(a[2]), "r"(a[3]), "r"(b[0]), "r"(b[1]));
}

__device__ __forceinline__ void cp_async16(uint32_t saddr, const void* gaddr) {
    asm volatile("cp.async.cg.shared.global [%0], [%1], 16;" :: "r"(saddr), "l"(gaddr));
}
__device__ __forceinline__ void cp_commit() { asm volatile("cp.async.commit_group;"); }
template <int N> __device__ __forceinline__ void cp_wait() {
    asm volatile("cp.async.wait_group %0;" :: "n"(N));
}

__device__ __forceinline__ uint32_t pack2(__nv_bfloat16 a, __nv_bfloat16 b) {
    __nv_bfloat162 p; p.x = a; p.y = b;
    return *reinterpret_cast<uint32_t*>(&p);
}

// Dependency wait: thread 0 spins on up to two counters, then acquire+sync.
__device__ __forceinline__ void wait2(const int* c1, int t1, const int* c2, int t2) {
    if (threadIdx.x == 0) {
        while (*(volatile const int*)c1 < t1) __nanosleep(128);
        while (*(volatile const int*)c2 < t2) __nanosleep(128);
        __threadfence();
    }
    __syncthreads();
}

// Completion signal: all threads fence, sync, one thread bumps the counter.
__device__ __forceinline__ void signal(int* c) {
    __threadfence();
    __syncthreads();
    if (threadIdx.x == 0) atomicAdd(c, 1);
}

// ===========================================================================
// GEMM mainloop (BN=128): acc[4][8][4] += A[128,K] @ B[128,K]^T
//   128 threads = 4 warps (2M x 2N); warp tile 64x64. K-chunk 64.
//   ONE __syncthreads per k-chunk (loads for next stage issued after the sync;
//   only one cp.async group in flight, so wait<0> == previous stage landed).
// ===========================================================================
#define ROW_B   144
#define TILE_A_B (128 * ROW_B)   // 18432
#define STAGE_B  (2 * TILE_A_B)  // 36864
#define SMEM_128 (2 * STAGE_B)   // 73728

__device__ __forceinline__ void load_stage(
    const __nv_bfloat16* __restrict__ A, int lda,
    const __nv_bfloat16* __restrict__ B, int ldb,
    int stg, uint32_t sbase, int buf, int t)
{
    const size_t ko = (size_t)stg * 64;
    const uint32_t st = sbase + buf * STAGE_B;
#pragma unroll
    for (int i = 0; i < 8; i++) {
        const int c = t + i * 128;
        const int row = c >> 3, col = c & 7;
        cp_async16(st + row * ROW_B + col * 16,
                   reinterpret_cast<const char*>(A + (size_t)row * lda + ko) + col * 16);
    }
#pragma unroll
    for (int i = 0; i < 8; i++) {
        const int c = t + i * 128;
        const int row = c >> 3, col = c & 7;
        cp_async16(st + TILE_A_B + row * ROW_B + col * 16,
                   reinterpret_cast<const char*>(B + (size_t)row * ldb + ko) + col * 16);
    }
    cp_commit();
}

__device__ __forceinline__ void mma_mainloop(
    const __nv_bfloat16* __restrict__ A, int lda,
    const __nv_bfloat16* __restrict__ B, int ldb,
    int Kdim, char* smem, float acc[4][8][4])
{
    const int t    = threadIdx.x;
    const int lane = t & 31;
    const int warp = t >> 5;
    const int wm   = warp & 1;
    const int wn   = warp >> 1;
    const uint32_t sbase = smem_u32(smem);

    const int aRow = lane & 15;
    const int aK   = (lane >> 4) & 1;
    const int bRow = (lane & 7) | (((lane >> 4) & 1) << 3);
    const int bK   = (lane >> 3) & 1;
    const uint32_t aBase = (wm * 64 + aRow) * ROW_B + aK * 16;
    const uint32_t bBase = TILE_A_B + (wn * 64 + bRow) * ROW_B + bK * 16;

#pragma unroll
    for (int i = 0; i < 4; i++)
#pragma unroll
        for (int j = 0; j < 8; j++)
#pragma unroll
            for (int q = 0; q < 4; q++) acc[i][j][q] = 0.0f;

    const int nstg = Kdim >> 6;
    load_stage(A, lda, B, ldb, 0, sbase, 0, t);

    for (int i = 0; i < nstg; i++) {
        const int buf = i & 1;
        cp_wait<0>();        // stage i resident (sole outstanding group)
        __syncthreads();     // publish stage i; iter i-1 readers of buf^1 done
        if (i + 1 < nstg) load_stage(A, lda, B, ldb, i + 1, sbase, buf ^ 1, t);

        const uint32_t st = sbase + buf * STAGE_B;
#pragma unroll
        for (int step = 0; step < 4; step++) {
            const uint32_t ao = st + aBase + step * 32;
            const uint32_t bo = st + bBase + step * 32;

            uint32_t a[4][4], b[8][2];
#pragma unroll
            for (int mt = 0; mt < 4; mt++)
                ldsm_x4(a[mt][0], a[mt][1], a[mt][2], a[mt][3], ao + mt * 16 * ROW_B);
#pragma unroll
            for (int g = 0; g < 4; g++) {
                uint32_t r0, r1, r2, r3;
                ldsm_x4(r0, r1, r2, r3, bo + g * 16 * ROW_B);
                b[2 * g][0] = r0;     b[2 * g][1] = r1;
                b[2 * g + 1][0] = r2; b[2 * g + 1][1] = r3;
            }
#pragma unroll
            for (int mt = 0; mt < 4; mt++)
#pragma unroll
                for (int nt = 0; nt < 8; nt++) mma16816(acc[mt][nt], a[mt], b[nt]);
        }
    }
    __syncthreads();   // final: smem free for epilogue reuse
}

#define TSTRIDE 144

// ===========================================================================
// Phase bodies
// ===========================================================================
__device__ void do_qkv(int id, char* smem,
                       const float* bq, const float* bk, const float* bv)
{
    // id = y*24 + x*3 + z  (rowblock-major)
    const int y = id / 24;
    const int r = id % 24;
    const int x = r / 3;
    const int z = r % 3;
    const int m0 = y * 128, n0 = x * 128;

    const __nv_bfloat16* B = g_wt + (size_t)z * DIM * DIM;
    const float* bias = (z == 0) ? bq : (z == 1) ? bk : bv;

    float acc[4][8][4];
    mma_mainloop(g_x + (size_t)m0 * DIM, DIM, B + (size_t)n0 * DIM, DIM, DIM, smem, acc);

    const int t = threadIdx.x;
    const int lane = t & 31, warp = t >> 5;
    const int wm = warp & 1, wn = warp >> 1;

    if (z < 2) {
        __nv_bfloat16* O = (z == 0) ? g_q : g_k;
#pragma unroll
        for (int mt = 0; mt < 4; mt++)
#pragma unroll
            for (int nt = 0; nt < 8; nt++) {
                const int rr = m0 + wm * 64 + mt * 16 + (lane >> 2);
                const int cc = n0 + wn * 64 + nt * 8 + (lane & 3) * 2;
                const float b0 = bias[cc], b1 = bias[cc + 1];
#pragma unroll
                for (int h = 0; h < 2; h++) {
                    const size_t o = (size_t)(rr + h * 8) * DIM + cc;
                    *reinterpret_cast<uint32_t*>(O + o) =
                        pack2(__float2bfloat16(acc[mt][nt][2 * h] + b0),
                              __float2bfloat16(acc[mt][nt][2 * h + 1] + b1));
                }
            }
        signal((z == 0) ? CNT_Q + y : CNT_K + y);
    } else {
        // V: stage transposed tile in smem, write V^T (g_vt[b][d][s])
        __nv_bfloat16* stile = reinterpret_cast<__nv_bfloat16*>(smem);
#pragma unroll
        for (int mt = 0; mt < 4; mt++)
#pragma unroll
            for (int nt = 0; nt < 8; nt++) {
                const int rl = wm * 64 + mt * 16 + (lane >> 2);
                const int cl = wn * 64 + nt * 8 + (lane & 3) * 2;
                const float b0 = bias[n0 + cl], b1 = bias[n0 + cl + 1];
#pragma unroll
                for (int h = 0; h < 2; h++) {
                    stile[(cl)     * TSTRIDE + rl + h * 8] =
                        __float2bfloat16(acc[mt][nt][2 * h] + b0);
                    stile[(cl + 1) * TSTRIDE + rl + h * 8] =
                        __float2bfloat16(acc[mt][nt][2 * h + 1] + b1);
                }
            }
        __syncthreads();
        const int bb = m0 >> 11;
        const int s0 = m0 & 2047;
        __nv_bfloat16* T = g_vt + (size_t)bb * DIM * SEQ;
#pragma unroll
        for (int pass = 0; pass < 16; pass++) {
            const int dl = pass * 8 + (t >> 4);
            const int sc = (t & 15) * 8;
            uint4 v = *reinterpret_cast<const uint4*>(stile + dl * TSTRIDE + sc);
            *reinterpret_cast<uint4*>(T + (size_t)(n0 + dl) * SEQ + s0 + sc) = v;
        }
        signal(CNT_V + x * 4 + (y >> 4));
    }
}

// scores (BN=128) + exp + partial row sums: P (bf16) + g_psum[row][16]
__device__ void do_scores(int id, char* smem)
{
    // id = rb*16 + n ; rb = b*16 + m
    const int rb = id / 16;
    const int n  = id % 16;
    const int b  = rb / 16;
    const int m0 = (rb % 16) * 128;
    const int n0 = n * 128;

    wait2(CNT_Q + rb, 8, CNT_K + b * 16 + n, 8);

    const size_t qo = (size_t)b * SEQ * DIM;
    float acc[4][8][4];
    mma_mainloop(g_q + qo + (size_t)m0 * DIM, DIM,
                 g_k + qo + (size_t)n0 * DIM, DIM, DIM, smem, acc);

    const int t = threadIdx.x;
    const int lane = t & 31, warp = t >> 5;
    const int wm = warp & 1, wn = warp >> 1;
    __nv_bfloat16* out = g_p + (size_t)b * SEQ * SEQ;

    float rsum[4][2];
#pragma unroll
    for (int mt = 0; mt < 4; mt++) { rsum[mt][0] = 0.f; rsum[mt][1] = 0.f; }

#pragma unroll
    for (int mt = 0; mt < 4; mt++)
#pragma unroll
        for (int nt = 0; nt < 8; nt++) {
            const int rr = m0 + wm * 64 + mt * 16 + (lane >> 2);
            const int cc = n0 + wn * 64 + nt * 8 + (lane & 3) * 2;
#pragma unroll
            for (int h = 0; h < 2; h++) {
                float e0 = __expf(acc[mt][nt][2 * h]     * 0.03125f);
                float e1 = __expf(acc[mt][nt][2 * h + 1] * 0.03125f);
                *reinterpret_cast<uint32_t*>(out + (size_t)(rr + h * 8) * SEQ + cc) =
                    pack2(__float2bfloat16(e0), __float2bfloat16(e1));
                rsum[mt][h] += e0 + e1;
            }
        }

#pragma unroll
    for (int mt = 0; mt < 4; mt++)
#pragma unroll
        for (int h = 0; h < 2; h++) {
            rsum[mt][h] += __shfl_xor_sync(0xffffffffu, rsum[mt][h], 1);
            rsum[mt][h] += __shfl_xor_sync(0xffffffffu, rsum[mt][h], 2);
        }

    float* sums = reinterpret_cast<float*>(smem);   // [128][2]
    if ((lane & 3) == 0) {
#pragma unroll
        for (int mt = 0; mt < 4; mt++)
#pragma unroll
            for (int h = 0; h < 2; h++) {
                const int row = wm * 64 + mt * 16 + (lane >> 2) + h * 8;
                sums[row * 2 + wn] = rsum[mt][h];
            }
    }
    __syncthreads();
    if (t < 128) {
        float s = sums[t * 2] + sums[t * 2 + 1];
        g_psum[((size_t)b * SEQ + m0 + t) * 16 + n] = s;
    }
    signal(CNT_S + rb);
}

// ctx (BN=128): (P @ V^T normalized) + X residual; LN partials to g_lnp[row][16]
__device__ void do_ctx(int id, char* smem, float* outp, const float* x)
{
    // id = rb*8 + n
    const int rb = id / 8;
    const int n  = id % 8;
    const int b  = rb / 16;
    const int m0 = (rb % 16) * 128;
    const int n0 = n * 128;
    const int t = threadIdx.x;
    const int lane = t & 31, warp = t >> 5;
    const int wm = warp & 1, wn = warp >> 1;
    const size_t rowbase = (size_t)b * SEQ;

    wait2(CNT_S + rb, 16, CNT_V + n * 4 + b, 16);

    // Prologue: 1/rowsum for this tile's 128 rows (16 partials each)
    {
        float* sinv = reinterpret_cast<float*>(smem);
        if (t < 128) {
            const float4* pp =
                reinterpret_cast<const float4*>(g_psum + (rowbase + m0 + t) * 16);
            float4 a = pp[0], bb = pp[1], c = pp[2], d = pp[3];
            float s = ((a.x + a.y) + (a.z + a.w)) + ((bb.x + bb.y) + (bb.z + bb.w)) +
                      ((c.x + c.y) + (c.z + c.w)) + ((d.x + d.y) + (d.z + d.w));
            sinv[t] = 1.0f / s;
        }
        __syncthreads();
    }
    float invr[4][2];
#pragma unroll
    for (int mt = 0; mt < 4; mt++)
#pragma unroll
        for (int h = 0; h < 2; h++)
            invr[mt][h] = reinterpret_cast<const float*>(smem)
                          [wm * 64 + mt * 16 + (lane >> 2) + h * 8];
    __syncthreads();

    float acc[4][8][4];
    mma_mainloop(g_p + (size_t)b * SEQ * SEQ + (size_t)m0 * SEQ, SEQ,
                 g_vt + (size_t)b * (size_t)DIM * SEQ + (size_t)n0 * SEQ, SEQ,
                 SEQ, smem, acc);

    float* out = outp + rowbase * DIM;
    const float* xin = x + rowbase * DIM;

    float s1[4][2], s2[4][2];
#pragma unroll
    for (int mt = 0; mt < 4; mt++) { s1[mt][0] = s1[mt][1] = s2[mt][0] = s2[mt][1] = 0.f; }

#pragma unroll
    for (int mt = 0; mt < 4; mt++)
#pragma unroll
        for (int nt = 0; nt < 8; nt++) {
            const int rr = m0 + wm * 64 + mt * 16 + (lane >> 2);
            const int cc = n0 + wn * 64 + nt * 8 + (lane & 3) * 2;
#pragma unroll
            for (int h = 0; h < 2; h++) {
                const size_t o = (size_t)(rr + h * 8) * DIM + cc;
                float2 xi = *reinterpret_cast<const float2*>(xin + o);
                float v0 = acc[mt][nt][2 * h]     * invr[mt][h] + xi.x;
                float v1 = acc[mt][nt][2 * h + 1] * invr[mt][h] + xi.y;
                *reinterpret_cast<float2*>(out + o) = make_float2(v0, v1);
                s1[mt][h] += v0 + v1;
                s2[mt][h] += v0 * v0 + v1 * v1;
            }
        }

#pragma unroll
    for (int mt = 0; mt < 4; mt++)
#pragma unroll
        for (int h = 0; h < 2; h++) {
            s1[mt][h] += __shfl_xor_sync(0xffffffffu, s1[mt][h], 1);
            s1[mt][h] += __shfl_xor_sync(0xffffffffu, s1[mt][h], 2);
            s2[mt][h] += __shfl_xor_sync(0xffffffffu, s2[mt][h], 1);
            s2[mt][h] += __shfl_xor_sync(0xffffffffu, s2[mt][h], 2);
        }

    float* sums = reinterpret_cast<float*>(smem);   // [128][2 warps][2 stats]
    if ((lane & 3) == 0) {
#pragma unroll
        for (int mt = 0; mt < 4; mt++)
#pragma unroll
            for (int h = 0; h < 2; h++) {
                const int row = wm * 64 + mt * 16 + (lane >> 2) + h * 8;
                sums[row * 4 + wn * 2 + 0] = s1[mt][h];
                sums[row * 4 + wn * 2 + 1] = s2[mt][h];
            }
    }
    __syncthreads();
    if (t < 128) {
        const size_t row = rowbase + m0 + t;
        g_lnp[row * 16 + n]     = sums[t * 4] + sums[t * 4 + 2];
        g_lnp[row * 16 + 8 + n] = sums[t * 4 + 1] + sums[t * 4 + 3];
    }
    signal(CNT_C + rb);
}

__device__ void do_ln(int id, const float* gamma, const float* beta, float* io)
{
    wait2(CNT_C + (id >> 2), 8, CNT_C + (id >> 2), 8);

    const int warp = threadIdx.x >> 5, lane = threadIdx.x & 31;
    const int row0 = id * 32 + warp * 8;
#pragma unroll
    for (int j = 0; j < 8; j++) {
        const int row = row0 + j;
        float v1 = (lane < 8) ? g_lnp[(size_t)row * 16 + lane] : 0.f;
        float v2 = (lane < 8) ? g_lnp[(size_t)row * 16 + 8 + lane] : 0.f;
#pragma unroll
        for (int o = 16; o > 0; o >>= 1) {
            v1 += __shfl_xor_sync(0xffffffffu, v1, o);
            v2 += __shfl_xor_sync(0xffffffffu, v2, o);
        }
        const float mu = v1 * (1.0f / DIM);
        const float var = v2 * (1.0f / DIM) - mu * mu;
        const float w = rsqrtf(var + 1e-3f);

        float* p = io + (size_t)row * DIM;
#pragma unroll
        for (int i = 0; i < 8; i++) {
            const int idx = i * 128 + lane * 4;
            float4 v = *reinterpret_cast<const float4*>(p + idx);
            float4 g = *reinterpret_cast<const float4*>(gamma + idx);
            float4 bb = *reinterpret_cast<const float4*>(beta + idx);
            *reinterpret_cast<float4*>(p + idx) =
                make_float4((v.x - mu) * w * g.x + bb.x, (v.y - mu) * w * g.y + bb.y,
                            (v.z - mu) * w * g.z + bb.z, (v.w - mu) * w * g.w + bb.w);
        }
    }
}

// ===========================================================================
// Persistent megakernel
// ===========================================================================
__global__ void __launch_bounds__(128, 3) mega(
    float* __restrict__ out, const float* __restrict__ x,
    const float* __restrict__ bq, const float* __restrict__ bk,
    const float* __restrict__ bv,
    const float* __restrict__ gamma, const float* __restrict__ beta)
{
    extern __shared__ __align__(16) char smem[];
    __shared__ int s_tile;

    for (;;) {
        if (threadIdx.x == 0) s_tile = atomicAdd(TILE_CTR, 1);
        __syncthreads();
        const int tile = s_tile;
        if (tile >= TOTAL_TILES) break;

        if (tile < SC_BASE)        do_qkv(tile, smem, bq, bk, bv);
        else if (tile < CTX_BASE)  do_scores(tile - SC_BASE, smem);
        else if (tile < LN_BASE)   do_ctx(tile - CTX_BASE, smem, out, x);
        else                       do_ln(tile - LN_BASE, gamma, beta, out);

        __syncthreads();   // protect s_tile before next grab
    }
}

// ===========================================================================
// Conversion kernel (full-grid, separate launch — max parallelism)
// ===========================================================================
__global__ void __launch_bounds__(256) conv_all(
    const float* __restrict__ x,
    const float* __restrict__ Wq, const float* __restrict__ Wk, const float* __restrict__ Wv)
{
    const int z = blockIdx.z;
    if (z < 3) {
        __shared__ float s[32][33];
        const float* W = (z == 0) ? Wq : (z == 1) ? Wk : Wv;
        __nv_bfloat16* o = g_wt + (size_t)z * DIM * DIM;
        const int n0 = blockIdx.x * 32, k0 = blockIdx.y * 32;
        const int tx = threadIdx.x & 31, ty = threadIdx.x >> 5;
#pragma unroll
        for (int i = 0; i < 32; i += 8)
            s[ty + i][tx] = W[(size_t)(k0 + ty + i) * DIM + n0 + tx];
        __syncthreads();
#pragma unroll
        for (int i = 0; i < 32; i += 8)
            o[(size_t)(n0 + ty + i) * DIM + k0 + tx] = __float2bfloat16(s[tx][ty + i]);
    } else {
        const int bid = blockIdx.y * 32 + blockIdx.x;
        const int base = bid * 2048 + threadIdx.x;
#pragma unroll
        for (int k = 0; k < 8; k++) {
            const int i = base + k * 256;
            float4 v = reinterpret_cast<const float4*>(x)[i];
            reinterpret_cast<uint2*>(g_x)[i] =
                make_uint2(pack2(__float2bfloat16(v.x), __float2bfloat16(v.y)),
                           pack2(__float2bfloat16(v.z), __float2bfloat16(v.w)));
        }
    }
}

// ===========================================================================
// Launch
// ===========================================================================
extern "C" void kernel_launch(void* const* d_in, const int* in_sizes, int n_in,
                              void* d_out, int out_size)
{
    const float* X  = (const float*)d_in[0];
    const float* Wq = (const float*)d_in[1];
    const float* bq = (const float*)d_in[2];
    const float* Wk = (const float*)d_in[3];
    const float* bk = (const float*)d_in[4];
    const float* Wv = (const float*)d_in[5];
    const float* bv = (const float*)d_in[6];
    const float* gm = (const float*)d_in[7];
    const float* bt = (const float*)d_in[8];
    float* out = (float*)d_out;

    cudaFuncSetAttribute(mega, cudaFuncAttributeMaxDynamicSharedMemorySize, SMEM_128);

    // reset scheduler state (single async memset; graph-capturable)
    void* sched_addr = nullptr;
    cudaGetSymbolAddress(&sched_addr, g_sched);
    cudaMemsetAsync(sched_addr, 0, 512 * sizeof(int));

    // conversions at full grid parallelism
    conv_all<<<dim3(32, 32, 4), 256>>>(X, Wq, Wk, Wv);

    // persistent megakernel: qkv -> scores -> ctx -> LN via tile queue
    mega<<<444, 128, SMEM_128>>>(out, X, bq, bk, bv, gm, bt);
}